// round 3
// baseline (speedup 1.0000x reference)
#include <cuda_runtime.h>
#include <math.h>

#define BB 16
#define SS 8
#define CC 3
#define KK 6
#define HW 16384
#define CHUNK 256
#define NCHUNK (HW/CHUNK)     // 64
#define NTHREADS 288          // 9 warps
#define EPSF 1.1920928955078125e-07f

// per-chunk partial slots:
//   F/XX: s*108 + k*18 + j  (j<12: F[a][b], j in 12..17: XX sym3)   [0,864)
//   Sec/gps: 864 + k*11 + j (j<10: sym4 Sec, j=10: gp sum)          [864,930)
#define NSLOT 930

__device__ float4 g_shp[BB*SS*HW];     // packed shifted (x0,x1,x2,0)
__device__ float4 g_imgp[BB*HW];       // packed padded  (p0,p1,p2,1)
__device__ float  g_part[BB*NCHUNK*NSLOT];
__device__ float  g_mom[BB*NSLOT];
__device__ float  g_ops[BB*SS*KK*12];
__device__ float  g_siginv[BB*SS*KK*8];
__device__ float  g_ldsum[BB*KK];

// ---------------- one-time packing ----------------
__global__ void pack_kernel(const float* __restrict__ img, const float* __restrict__ shifted)
{
    const int plane = blockIdx.y;            // [0, BB*SS + BB)
    const int pix = blockIdx.x*256 + threadIdx.x;
    if (plane < BB*SS) {
        const float* src = shifted + (size_t)plane*CC*HW;
        g_shp[(size_t)plane*HW + pix] = make_float4(src[pix], src[HW+pix], src[2*HW+pix], 0.f);
    } else {
        const int u = plane - BB*SS;
        const float* src = img + (size_t)u*CC*HW;
        g_imgp[(size_t)u*HW + pix] = make_float4(src[pix], src[HW+pix], src[2*HW+pix], 1.f);
    }
}

// MODE 0: softmax(pred) -> gp, accumulate moments
// MODE 1: quad -> gen -> softmax(pred+gen) -> gp, accumulate moments
// MODE 2: quad -> gen -> write output
template<int MODE>
__global__ __launch_bounds__(NTHREADS, 2)
void accum_kernel(const float* __restrict__ pred, float* __restrict__ out)
{
    __shared__ float  s_gp[KK][CHUNK];      // 6 KB
    __shared__ float4 s_ops4[SS*KK*3];      // 2.25 KB
    __shared__ float4 s_sinv4[SS*KK*2];     // 1.5 KB
    __shared__ float  s_ld[KK];

    const int u    = blockIdx.y;
    const int base = blockIdx.x * CHUNK;
    const int tid  = threadIdx.x;

    if (MODE >= 1) {
        const float4* go = (const float4*)(g_ops + u*SS*KK*12);
        for (int i = tid; i < SS*KK*3; i += NTHREADS) s_ops4[i] = go[i];
        const float4* gs = (const float4*)(g_siginv + u*SS*KK*8);
        for (int i = tid; i < SS*KK*2; i += NTHREADS) s_sinv4[i] = gs[i];
        if (tid < KK) s_ld[tid] = g_ldsum[u*KK + tid];
        __syncthreads();
    }

    const float4* shU  = g_shp + (size_t)u*SS*HW;
    const float4* imgU = g_imgp + (size_t)u*HW;
    const float* predU = pred + (size_t)u*KK*HW;

    // ---- phase 1: per-pixel quad / softmax ----
    if (tid < CHUNK) {
        const int pix = base + tid;
        const float4 pb = imgU[pix];

        float q[KK];
        #pragma unroll
        for (int k = 0; k < KK; k++) q[k] = 0.f;

        if (MODE >= 1) {
            #pragma unroll
            for (int s = 0; s < SS; s++) {
                const float4 x = shU[s*HW + pix];
                #pragma unroll
                for (int k = 0; k < KK; k++) {
                    const int m = (s*KK + k);
                    const float4 o0 = s_ops4[m*3+0];
                    const float4 o1 = s_ops4[m*3+1];
                    const float4 o2 = s_ops4[m*3+2];
                    const float d0 = x.x - (o0.x*pb.x + o0.y*pb.y + o0.z*pb.z + o0.w);
                    const float d1 = x.y - (o1.x*pb.x + o1.y*pb.y + o1.z*pb.z + o1.w);
                    const float d2 = x.z - (o2.x*pb.x + o2.y*pb.y + o2.z*pb.z + o2.w);
                    const float4 si0 = s_sinv4[m*2+0]; // s00 s01 s02 s11
                    const float4 si1 = s_sinv4[m*2+1]; // s12 s22 - -
                    q[k] += si0.x*d0*d0 + si0.w*d1*d1 + si1.y*d2*d2
                          + 2.f*(si0.y*d0*d1 + si0.z*d0*d2 + si1.x*d1*d2);
                }
            }
        }

        if (MODE == 2) {
            #pragma unroll
            for (int k = 0; k < KK; k++)
                out[((size_t)u*KK + k)*HW + pix] = -0.5f*q[k] - 0.5f*s_ld[k];
        } else {
            float lg[KK];
            float mx = -1e30f;
            #pragma unroll
            for (int k = 0; k < KK; k++) {
                const float gen = (MODE >= 1) ? (-0.5f*q[k] - 0.5f*s_ld[k]) : 0.f;
                lg[k] = predU[k*HW + pix] + gen;
                mx = fmaxf(mx, lg[k]);
            }
            float sum = 0.f;
            #pragma unroll
            for (int k = 0; k < KK; k++) { lg[k] = __expf(lg[k] - mx); sum += lg[k]; }
            const float inv = 1.f / sum;
            #pragma unroll
            for (int k = 0; k < KK; k++) s_gp[k][tid] = lg[k]*inv + EPSF;
        }
    }
    if (MODE == 2) return;
    __syncthreads();

    // ---- phase 2: moment accumulation ----
    const int warp = tid >> 5, lane = tid & 31;
    float* part = g_part + (size_t)(u*NCHUNK + blockIdx.x)*NSLOT;

    if (warp < SS) {
        const int s = warp;
        const float4* xs = shU + s*HW + base;
        #pragma unroll 1
        for (int g = 0; g < 2; g++) {
            const int k0 = g*3;
            float acc[54];
            #pragma unroll
            for (int j = 0; j < 54; j++) acc[j] = 0.f;
            #pragma unroll
            for (int i = 0; i < CHUNK/32; i++) {
                const int p = lane + 32*i;
                const float4 x  = xs[p];
                const float4 pb = imgU[base + p];
                #pragma unroll
                for (int kk = 0; kk < 3; kk++) {
                    float* a = acc + kk*18;
                    const float wk = s_gp[k0+kk][p];
                    const float t0 = x.x*wk, t1 = x.y*wk, t2 = x.z*wk;
                    a[0]  += t0*pb.x; a[1]  += t0*pb.y; a[2]  += t0*pb.z; a[3]  += t0;
                    a[4]  += t1*pb.x; a[5]  += t1*pb.y; a[6]  += t1*pb.z; a[7]  += t1;
                    a[8]  += t2*pb.x; a[9]  += t2*pb.y; a[10] += t2*pb.z; a[11] += t2;
                    a[12] += t0*x.x; a[13] += t0*x.y; a[14] += t0*x.z;
                    a[15] += t1*x.y; a[16] += t1*x.z; a[17] += t2*x.z;
                }
            }
            #pragma unroll
            for (int j = 0; j < 54; j++) {
                float v = acc[j];
                #pragma unroll
                for (int off = 16; off > 0; off >>= 1) v += __shfl_down_sync(0xffffffffu, v, off);
                if (lane == 0) part[s*108 + (k0 + j/18)*18 + (j%18)] = v;
            }
        }
    } else {
        // warp 8: sym4 Sec moments + gp sums, k-blocked by 3
        #pragma unroll 1
        for (int g = 0; g < 2; g++) {
            const int k0 = g*3;
            float acc[33];
            #pragma unroll
            for (int j = 0; j < 33; j++) acc[j] = 0.f;
            #pragma unroll
            for (int i = 0; i < CHUNK/32; i++) {
                const int p = lane + 32*i;
                const float4 pb = imgU[base + p];
                #pragma unroll
                for (int kk = 0; kk < 3; kk++) {
                    float* a = acc + kk*11;
                    const float wk = s_gp[k0+kk][p];
                    const float w0 = wk*pb.x, w1 = wk*pb.y, w2 = wk*pb.z;
                    a[0] += w0*pb.x; a[1] += w0*pb.y; a[2] += w0*pb.z; a[3] += w0;
                    a[4] += w1*pb.y; a[5] += w1*pb.z; a[6] += w1;
                    a[7] += w2*pb.z; a[8] += w2;
                    a[9] += wk; a[10] += wk;
                }
            }
            #pragma unroll
            for (int j = 0; j < 33; j++) {
                float v = acc[j];
                #pragma unroll
                for (int off = 16; off > 0; off >>= 1) v += __shfl_down_sync(0xffffffffu, v, off);
                if (lane == 0) part[864 + (k0 + j/11)*11 + (j%11)] = v;
            }
        }
    }
}

// ---------------- parallel fixed-order chunk reduce ----------------
__global__ void reduce_kernel()
{
    const int u = blockIdx.y;
    const int slot = blockIdx.x*128 + threadIdx.x;
    if (slot >= NSLOT) return;
    const float* p = g_part + (size_t)u*NCHUNK*NSLOT + slot;
    float v0=0,v1=0,v2=0,v3=0;
    #pragma unroll
    for (int c = 0; c < NCHUNK; c += 4) {
        v0 += p[(size_t)(c+0)*NSLOT];
        v1 += p[(size_t)(c+1)*NSLOT];
        v2 += p[(size_t)(c+2)*NSLOT];
        v3 += p[(size_t)(c+3)*NSLOT];
    }
    g_mom[u*NSLOT + slot] = (v0+v1)+(v2+v3);
}

// ---------------- per-u solve: ops + closed-form sigma + inverse + logdet ----------------
__global__ void solve_kernel()
{
    __shared__ float m[NSLOT];
    __shared__ float s_Inv[KK][16];
    __shared__ float s_norm[KK];
    __shared__ float s_pn[KK];
    __shared__ float s_ld48[SS*KK];

    const int u = blockIdx.x;
    const int t = threadIdx.x;

    for (int i = t; i < NSLOT; i += 64) m[i] = g_mom[u*NSLOT + i];
    __syncthreads();

    if (t < KK) {
        const int k = t;
        const float* sec = m + 864 + k*11;
        const float trace = sec[0] + sec[4] + sec[7] + sec[9];
        const float norm = 1.f / trace;
        s_norm[k] = norm;
        s_pn[k] = 1.f / sec[10];

        float M[4][4], Inv[4][4];
        M[0][0]=sec[0]; M[0][1]=sec[1]; M[0][2]=sec[2]; M[0][3]=sec[3];
        M[1][0]=sec[1]; M[1][1]=sec[4]; M[1][2]=sec[5]; M[1][3]=sec[6];
        M[2][0]=sec[2]; M[2][1]=sec[5]; M[2][2]=sec[7]; M[2][3]=sec[8];
        M[3][0]=sec[3]; M[3][1]=sec[6]; M[3][2]=sec[8]; M[3][3]=sec[9];
        for (int i = 0; i < 4; i++) {
            for (int j = 0; j < 4; j++) { M[i][j] *= norm; Inv[i][j] = (i==j)?1.f:0.f; }
            M[i][i] += EPSF;
        }
        for (int col = 0; col < 4; col++) {
            int piv = col; float best = fabsf(M[col][col]);
            for (int r = col+1; r < 4; r++) {
                const float v = fabsf(M[r][col]);
                if (v > best) { best = v; piv = r; }
            }
            if (piv != col) {
                for (int j = 0; j < 4; j++) {
                    float tmp=M[col][j]; M[col][j]=M[piv][j]; M[piv][j]=tmp;
                    tmp=Inv[col][j]; Inv[col][j]=Inv[piv][j]; Inv[piv][j]=tmp;
                }
            }
            const float d = 1.f / M[col][col];
            for (int j = 0; j < 4; j++) { M[col][j] *= d; Inv[col][j] *= d; }
            for (int r = 0; r < 4; r++) {
                if (r == col) continue;
                const float f = M[r][col];
                for (int j = 0; j < 4; j++) { M[r][j] -= f*M[col][j]; Inv[r][j] -= f*Inv[col][j]; }
            }
        }
        for (int i = 0; i < 16; i++) s_Inv[k][i] = Inv[i/4][i%4];
    }
    __syncthreads();

    if (t < SS*KK) {
        const int s = t / KK, k = t % KK;
        const float norm = s_norm[k];
        const float pn   = s_pn[k];
        const float* F  = m + s*108 + k*18;   // [3][4]
        const float* XX = F + 12;             // sym3
        const float* Sec10 = m + 864 + k*11;

        float Sec[4][4];
        Sec[0][0]=Sec10[0]; Sec[0][1]=Sec10[1]; Sec[0][2]=Sec10[2]; Sec[0][3]=Sec10[3];
        Sec[1][0]=Sec10[1]; Sec[1][1]=Sec10[4]; Sec[1][2]=Sec10[5]; Sec[1][3]=Sec10[6];
        Sec[2][0]=Sec10[2]; Sec[2][1]=Sec10[5]; Sec[2][2]=Sec10[7]; Sec[2][3]=Sec10[8];
        Sec[3][0]=Sec10[3]; Sec[3][1]=Sec10[6]; Sec[3][2]=Sec10[8]; Sec[3][3]=Sec10[9];

        float O[3][4];
        for (int a = 0; a < 3; a++)
            for (int b = 0; b < 4; b++) {
                float v = 0.f;
                for (int c = 0; c < 4; c++) v += (F[a*4+c]*norm) * s_Inv[k][c*4+b];
                O[a][b] = v;
            }
        float* go = g_ops + u*SS*KK*12 + t*12;
        for (int i = 0; i < 12; i++) go[i] = O[i/4][i%4];

        // sigma = pn*(XX - F O^T - (F O^T)^T + O Sec O^T) + EPS I
        float H[3][3];
        for (int a = 0; a < 3; a++)
            for (int b = 0; b < 3; b++) {
                float v = 0.f;
                for (int c = 0; c < 4; c++) v += F[a*4+c]*O[b][c];
                H[a][b] = v;
            }
        float G[3][4];
        for (int a = 0; a < 3; a++)
            for (int c = 0; c < 4; c++) {
                float v = 0.f;
                for (int cc = 0; cc < 4; cc++) v += O[a][cc]*Sec[cc][c];
                G[a][c] = v;
            }
        float GO[3][3];
        for (int a = 0; a < 3; a++)
            for (int b = a; b < 3; b++) {
                float v = 0.f;
                for (int c = 0; c < 4; c++) v += G[a][c]*O[b][c];
                GO[a][b] = v;
            }
        const float sa = pn*(XX[0] - 2.f*H[0][0]       + GO[0][0]) + EPSF;
        const float sb = pn*(XX[1] - H[0][1] - H[1][0] + GO[0][1]);
        const float sc = pn*(XX[2] - H[0][2] - H[2][0] + GO[0][2]);
        const float sd = pn*(XX[3] - 2.f*H[1][1]       + GO[1][1]) + EPSF;
        const float se = pn*(XX[4] - H[1][2] - H[2][1] + GO[1][2]);
        const float sf = pn*(XX[5] - 2.f*H[2][2]       + GO[2][2]) + EPSF;

        const float A  = sd*sf - se*se;
        const float Bc = sc*se - sb*sf;
        const float Cc = sb*se - sc*sd;
        const float det = sa*A + sb*Bc + sc*Cc;
        const float idet = 1.f / det;

        float* Si = g_siginv + ((size_t)u*SS*KK + t)*8;
        Si[0] = A*idet;
        Si[1] = Bc*idet;
        Si[2] = Cc*idet;
        Si[3] = (sa*sf - sc*sc)*idet;
        Si[4] = (sb*sc - sa*se)*idet;
        Si[5] = (sa*sd - sb*sb)*idet;
        Si[6] = 0.f; Si[7] = 0.f;

        s_ld48[t] = logf(det);
    }
    __syncthreads();
    if (t < KK) {
        float v = 0.f;
        for (int s = 0; s < SS; s++) v += s_ld48[s*KK + t];
        g_ldsum[u*KK + t] = v;
    }
}

extern "C" void kernel_launch(void* const* d_in, const int* in_sizes, int n_in,
                              void* d_out, int out_size)
{
    const float* img = nullptr;
    const float* sh = nullptr;
    const float* pred = nullptr;
    for (int i = 0; i < n_in; i++) {
        if (in_sizes[i] == BB*CC*HW)         img  = (const float*)d_in[i];
        else if (in_sizes[i] == BB*SS*CC*HW) sh   = (const float*)d_in[i];
        else if (in_sizes[i] == BB*KK*HW)    pred = (const float*)d_in[i];
    }
    float* out = (float*)d_out;

    dim3 gpack(HW/256, BB*SS + BB);
    pack_kernel<<<gpack, 256>>>(img, sh);

    dim3 grid(NCHUNK, BB);
    dim3 gred(8, BB);

    accum_kernel<0><<<grid, NTHREADS>>>(pred, out);
    reduce_kernel<<<gred, 128>>>();
    solve_kernel<<<BB, 64>>>();
    accum_kernel<1><<<grid, NTHREADS>>>(pred, out);
    reduce_kernel<<<gred, 128>>>();
    solve_kernel<<<BB, 64>>>();
    accum_kernel<1><<<grid, NTHREADS>>>(pred, out);
    reduce_kernel<<<gred, 128>>>();
    solve_kernel<<<BB, 64>>>();
    accum_kernel<2><<<grid, NTHREADS>>>(pred, out);
}